// round 10
// baseline (speedup 1.0000x reference)
#include <cuda_runtime.h>
#include <cuda_bf16.h>
#include <cuda_fp16.h>
#include <cstdint>

#define B_  4
#define L_  2048
#define D_  1024
#define H_  16
#define HD_ 64
#define M_  (B_*L_)   // 8192

// ---------------- scratch (__device__ globals; no allocs allowed) ----------------
__device__ __nv_bfloat16 g_xhi[(size_t)M_*D_], g_xlo[(size_t)M_*D_];
__device__ __nv_bfloat16 g_whi[(size_t)4*D_*D_], g_wlo[(size_t)4*D_*D_];
__device__ __half g_qh16[(size_t)B_*H_*L_*HD_], g_ql16[(size_t)B_*H_*L_*HD_];
__device__ __half g_k16[(size_t)B_*H_*L_*HD_];
__device__ __half g_v16[(size_t)B_*H_*L_*HD_];
__device__ __nv_bfloat16 g_ahi[(size_t)M_*D_], g_alo[(size_t)M_*D_];
__device__ __half g_u[(size_t)B_*H_*L_*L_];   // exp(s - m_running) scratch (fp16)

// ---------------- helpers ----------------
__device__ __forceinline__ uint32_t smem_u32(const void* p) {
    uint32_t a;
    asm("{ .reg .u64 t; cvta.to.shared.u64 t, %1; cvt.u32.u64 %0, t; }" : "=r"(a) : "l"(p));
    return a;
}
__device__ __forceinline__ void cpasync16(uint32_t dst, const void* src) {
    asm volatile("cp.async.cg.shared.global [%0], [%1], 16;" :: "r"(dst), "l"(src));
}
__device__ __forceinline__ void mma16816(float* d, const uint32_t* a, const uint32_t* b) {
    asm volatile(
        "mma.sync.aligned.m16n8k16.row.col.f32.bf16.bf16.f32 "
        "{%0,%1,%2,%3}, {%4,%5,%6,%7}, {%8,%9}, {%0,%1,%2,%3};"
        : "+f"(d[0]), "+f"(d[1]), "+f"(d[2]), "+f"(d[3])
        : "r"(a[0]), "r"(a[1]), "r"(a[2]), "r"(a[3]), "r"(b[0]), "r"(b[1]));
}
__device__ __forceinline__ void mma16816f(float* d, const uint32_t* a, const uint32_t* b) {
    asm volatile(
        "mma.sync.aligned.m16n8k16.row.col.f32.f16.f16.f32 "
        "{%0,%1,%2,%3}, {%4,%5,%6,%7}, {%8,%9}, {%0,%1,%2,%3};"
        : "+f"(d[0]), "+f"(d[1]), "+f"(d[2]), "+f"(d[3])
        : "r"(a[0]), "r"(a[1]), "r"(a[2]), "r"(a[3]), "r"(b[0]), "r"(b[1]));
}
__device__ __forceinline__ void ldm4(uint32_t* r, uint32_t a) {
    asm volatile("ldmatrix.sync.aligned.m8n8.x4.shared.b16 {%0,%1,%2,%3}, [%4];"
        : "=r"(r[0]), "=r"(r[1]), "=r"(r[2]), "=r"(r[3]) : "r"(a));
}
__device__ __forceinline__ void ldm4t(uint32_t* r, uint32_t a) {
    asm volatile("ldmatrix.sync.aligned.m8n8.x4.trans.shared.b16 {%0,%1,%2,%3}, [%4];"
        : "=r"(r[0]), "=r"(r[1]), "=r"(r[2]), "=r"(r[3]) : "r"(a));
}
__device__ __forceinline__ uint32_t ldmA_addr(uint32_t base, int S, int row0, int lane) {
    int lr = lane & 7, sel = lane >> 3;
    return base + (uint32_t)((row0 + lr + (sel & 1) * 8) * S + (sel & 2) * 2) * 4;
}
__device__ __forceinline__ uint32_t ldmB_addr(uint32_t base, int S, int n0, int lane) {
    int lr = lane & 7, sel = lane >> 3;
    return base + (uint32_t)((n0 + lr + (sel >> 1) * 8) * S + (sel & 1) * 4) * 4;
}
__device__ __forceinline__ uint32_t ldmBT_addr(uint32_t base, int S, int n0, int lane) {
    int lr = lane & 7, sel = lane >> 3;
    return base + (uint32_t)((lr + (sel & 1) * 8) * S + (n0 + (sel >> 1) * 8) / 2) * 4;
}
__device__ __forceinline__ uint32_t packhl(float a, float b) {   // bf16 pair
    __nv_bfloat162 t = __halves2bfloat162(__float2bfloat16(a), __float2bfloat16(b));
    return *(uint32_t*)&t;
}
__device__ __forceinline__ uint32_t packres(float a, float b, uint32_t hw) {
    __nv_bfloat162 hv = *(__nv_bfloat162*)&hw;
    return packhl(a - __bfloat162float(hv.x), b - __bfloat162float(hv.y));
}
__device__ __forceinline__ uint32_t pack16(float a, float b) {   // fp16 pair
    __half2 t; t.x = __float2half_rn(a); t.y = __float2half_rn(b);
    return *(uint32_t*)&t;
}
__device__ __forceinline__ uint32_t packres16(float a, float b, uint32_t hw) {
    __half2 hv = *(__half2*)&hw;
    return pack16(a - __half2float(hv.x), b - __half2float(hv.y));
}

// ---------------- fp32 -> bf16 hi/lo split (x and weights) ----------------
__global__ __launch_bounds__(256) void split_kernel(const float* __restrict__ src, int sel, int z, int n4)
{
    int i = blockIdx.x * blockDim.x + threadIdx.x;
    if (i >= n4) return;
    __nv_bfloat16 *hi, *lo;
    if (sel == 0) { hi = g_xhi; lo = g_xlo; }
    else          { hi = g_whi + (size_t)z * D_ * D_; lo = g_wlo + (size_t)z * D_ * D_; }
    float4 v = ((const float4*)src)[i];
    uint32_t h0 = packhl(v.x, v.y), h1 = packhl(v.z, v.w);
    uint32_t l0 = packres(v.x, v.y, h0), l1 = packres(v.z, v.w, h1);
    ((uint32_t*)(hi + 4 * (size_t)i))[0] = h0; ((uint32_t*)(hi + 4 * (size_t)i))[1] = h1;
    ((uint32_t*)(lo + 4 * (size_t)i))[0] = l0; ((uint32_t*)(lo + 4 * (size_t)i))[1] = l1;
}

// ---------------- HMMA GEMM (bf16 3-term): C[m,n] = sum_k X[m,k]*W[n,k] ----------------
#define SRW  36
#define MATW (128*SRW)
#define BUFW (4*MATW)
#define GSM_BYTES (2*BUFW*4)

template<int MODE>
__global__ __launch_bounds__(256) void gemm_mma(const float* __restrict__ bias, float* __restrict__ Out)
{
    extern __shared__ char smch[];
    const uint32_t sb = smem_u32(smch);

    const int tid = threadIdx.x, lane = tid & 31, wid = tid >> 5;
    const int wm = wid & 3, wn = wid >> 2;
    const int g = lane >> 2, cc = lane & 3;
    const int n0 = blockIdx.x * 128, m0 = blockIdx.y * 128;

    const __nv_bfloat16 *Ahp, *Alp, *Whp, *Wlp;
    int z = 0;
    if (MODE == 1) {
        z = blockIdx.z;
        Ahp = g_xhi; Alp = g_xlo;
        Whp = g_whi + (size_t)z * D_ * D_; Wlp = g_wlo + (size_t)z * D_ * D_;
    } else {
        Ahp = g_ahi; Alp = g_alo;
        Whp = g_whi + (size_t)3 * D_ * D_; Wlp = g_wlo + (size_t)3 * D_ * D_;
    }

    const int r = tid >> 1, half = tid & 1;
    const size_t garow = (size_t)(m0 + r) * D_ + half * 32;
    const size_t gbrow = (size_t)(n0 + r) * D_ + half * 32;
    const uint32_t sdst = sb + (uint32_t)(r * SRW + half * 16) * 4;

    auto issue_chunk = [&](int c) {
        const int k0 = c * 64;
        const uint32_t d0 = sdst + (uint32_t)((c & 1) * BUFW) * 4;
        const __nv_bfloat16* pa = Ahp + garow + k0;
        const __nv_bfloat16* pl = Alp + garow + k0;
        const __nv_bfloat16* pb = Whp + gbrow + k0;
        const __nv_bfloat16* pq = Wlp + gbrow + k0;
        #pragma unroll
        for (int j = 0; j < 4; j++) {
            cpasync16(d0 + j * 16,                 pa + j * 8);
            cpasync16(d0 + MATW * 4 + j * 16,      pl + j * 8);
            cpasync16(d0 + 2 * MATW * 4 + j * 16,  pb + j * 8);
            cpasync16(d0 + 3 * MATW * 4 + j * 16,  pq + j * 8);
        }
    };

    float d[2][8][4] = {};

    issue_chunk(0);
    asm volatile("cp.async.commit_group;" ::: "memory");

    for (int c = 0; c < 16; c++) {
        if (c < 15) {
            issue_chunk(c + 1);
            asm volatile("cp.async.commit_group;" ::: "memory");
            asm volatile("cp.async.wait_group 1;" ::: "memory");
        } else {
            asm volatile("cp.async.wait_group 0;" ::: "memory");
        }
        __syncthreads();

        const uint32_t bufb = sb + (uint32_t)((c & 1) * BUFW) * 4;
        const uint32_t aA0 = ldmA_addr(bufb, SRW, wm * 32, lane);
        const uint32_t aA1 = ldmA_addr(bufb, SRW, wm * 32 + 16, lane);
        uint32_t bB[2][2];
        #pragma unroll
        for (int nq = 0; nq < 2; nq++)
            #pragma unroll
            for (int pr = 0; pr < 2; pr++)
                bB[nq][pr] = ldmB_addr(bufb + 2 * MATW * 4, SRW, wn * 64 + nq * 32 + pr * 16, lane);

        #pragma unroll
        for (int ks = 0; ks < 4; ks++) {
            uint32_t ah[2][4], al[2][4];
            ldm4(ah[0], aA0 + ks * 32);
            ldm4(ah[1], aA1 + ks * 32);
            ldm4(al[0], aA0 + MATW * 4 + ks * 32);
            ldm4(al[1], aA1 + MATW * 4 + ks * 32);
            #pragma unroll
            for (int nq = 0; nq < 2; nq++)
                #pragma unroll
                for (int pr = 0; pr < 2; pr++) {
                    uint32_t bhp[4], blp[4];
                    ldm4(bhp, bB[nq][pr] + ks * 32);
                    ldm4(blp, bB[nq][pr] + MATW * 4 + ks * 32);
                    #pragma unroll
                    for (int hf = 0; hf < 2; hf++)
                        #pragma unroll
                        for (int mi = 0; mi < 2; mi++) {
                            float* dd = d[mi][nq * 4 + pr * 2 + hf];
                            mma16816(dd, ah[mi], bhp + hf * 2);
                            mma16816(dd, ah[mi], blp + hf * 2);
                            mma16816(dd, al[mi], bhp + hf * 2);
                        }
                }
        }
        __syncthreads();
    }

    // epilogue
    #pragma unroll
    for (int mi = 0; mi < 2; mi++) {
        const int row = m0 + wm * 32 + mi * 16 + g;
        #pragma unroll
        for (int ni = 0; ni < 8; ni++) {
            const int col = n0 + wn * 64 + ni * 8 + cc * 2;
            float* dd = d[mi][ni];
            if (MODE == 1) {
                int b = row >> 11, l = row & (L_ - 1);
                int hh = col >> 6, dp = col & 63;
                size_t base = ((size_t)(b * H_ + hh) * L_ + l) * HD_ + dp;
                uint32_t h0 = pack16(dd[0], dd[1]), h1 = pack16(dd[2], dd[3]);
                if (z == 0) {
                    *(uint32_t*)(g_qh16 + base)           = h0;
                    *(uint32_t*)(g_qh16 + base + 8 * HD_) = h1;
                    *(uint32_t*)(g_ql16 + base)           = packres16(dd[0], dd[1], h0);
                    *(uint32_t*)(g_ql16 + base + 8 * HD_) = packres16(dd[2], dd[3], h1);
                } else {
                    __half* dst = (z == 1) ? g_k16 : g_v16;
                    *(uint32_t*)(dst + base)           = h0;
                    *(uint32_t*)(dst + base + 8 * HD_) = h1;
                }
            } else {
                float bx = bias[col], by = bias[col + 1];
                *(float2*)(Out + (size_t)row * D_ + col) =
                    make_float2(dd[0] + bx, dd[1] + by);
                *(float2*)(Out + (size_t)(row + 8) * D_ + col) =
                    make_float2(dd[2] + bx, dd[3] + by);
            }
        }
    }
}

// ---------------- flash attention (fp16 MMA, online O, fp16 u scratch) ----------------
// CTA: (128 q-rows, 1 head). 32 key-chunks of 64. Warps: 4 m x 2 n (tile 32x32).
// smem words: Qhi 0..4608, Qlo 4608..9216, KV dbuf 9216..18432 (K 2304 + V 2304 each), P 18432..23040
#define SQW 36
#define WQLO 4608
#define WKV  9216
#define WPP  18432
#define ASM_BYTES (23040*4)   // 92160

__global__ __launch_bounds__(256) void attn_mma(float* __restrict__ A)
{
    extern __shared__ uint32_t s32[];
    __shared__ float ms[128], ls[128], sc[128];
    __shared__ float pm[128][2], pe[128][2];
    __shared__ float mc[32][128];

    const int tid = threadIdx.x, lane = tid & 31, wid = tid >> 5;
    const int g = lane >> 2, cc = lane & 3;
    const int wm3 = wid & 3, wn3 = wid >> 2;
    const int q0 = blockIdx.x * 128, h = blockIdx.y, b = blockIdx.z;
    const int bh = b * H_ + h;
    const __half* qh = g_qh16 + (size_t)bh * L_ * HD_;
    const __half* ql = g_ql16 + (size_t)bh * L_ * HD_;
    const __half* kp = g_k16  + (size_t)bh * L_ * HD_;
    const __half* vp = g_v16  + (size_t)bh * L_ * HD_;
    __half* ug = g_u + ((size_t)bh * L_ + q0) * L_;
    float* Ar = A + ((size_t)bh * L_ + q0) * L_;
    const uint32_t sb = smem_u32(s32);

    // Q 128x64 hi/lo -> smem
    {
        const int r = tid >> 1;
        const int s0 = (tid & 1) * 4;
        #pragma unroll
        for (int j = 0; j < 4; j++) {
            *(uint4*)&s32[r * SQW + (s0 + j) * 4]        = *(const uint4*)(qh + (size_t)(q0 + r) * HD_ + (s0 + j) * 8);
            *(uint4*)&s32[WQLO + r * SQW + (s0 + j) * 4] = *(const uint4*)(ql + (size_t)(q0 + r) * HD_ + (s0 + j) * 8);
        }
    }
    if (tid < 128) { ms[tid] = -1e30f; ls[tid] = 0.f; }

    auto loadKV = [&](int kt) {
        const uint32_t bo = WKV + (kt & 1) * 4608;
        const int r = tid >> 2;
        const int sp = (tid & 3) * 2;
        #pragma unroll
        for (int j = 0; j < 2; j++) {
            const int seg = sp + j;
            cpasync16(sb + (bo + r * SQW + seg * 4) * 4,        kp + (size_t)(kt * 64 + r) * HD_ + seg * 8);
            cpasync16(sb + (bo + 2304 + r * SQW + seg * 4) * 4, vp + (size_t)(kt * 64 + r) * HD_ + seg * 8);
        }
    };

    loadKV(0);
    asm volatile("cp.async.commit_group;" ::: "memory");

    const uint32_t aQh0 = ldmA_addr(sb, SQW, wm3 * 32, lane);
    const uint32_t aQh1 = ldmA_addr(sb, SQW, wm3 * 32 + 16, lane);
    const uint32_t aP0  = ldmA_addr(sb + WPP * 4, SQW, wm3 * 32, lane);
    const uint32_t aP1  = ldmA_addr(sb + WPP * 4, SQW, wm3 * 32 + 16, lane);

    float o[2][4][4] = {};

    for (int kt = 0; kt < 32; kt++) {
        if (kt < 31) {
            loadKV(kt + 1);
            asm volatile("cp.async.commit_group;" ::: "memory");
            asm volatile("cp.async.wait_group 1;" ::: "memory");
        } else {
            asm volatile("cp.async.wait_group 0;" ::: "memory");
        }
        __syncthreads();

        const uint32_t KVb = WKV + (kt & 1) * 4608;
        uint32_t bK[2];
        #pragma unroll
        for (int pr = 0; pr < 2; pr++)
            bK[pr] = ldmB_addr(sb + KVb * 4, SQW, wn3 * 32 + pr * 16, lane);

        // ---- S = Q K^T (2-term fp16) ----
        float d[2][4][4] = {};
        #pragma unroll
        for (int ks = 0; ks < 4; ks++) {
            uint32_t qhf[2][4], qlf[2][4];
            ldm4(qhf[0], aQh0 + ks * 32);
            ldm4(qhf[1], aQh1 + ks * 32);
            ldm4(qlf[0], aQh0 + WQLO * 4 + ks * 32);
            ldm4(qlf[1], aQh1 + WQLO * 4 + ks * 32);
            #pragma unroll
            for (int pr = 0; pr < 2; pr++) {
                uint32_t bk[4];
                ldm4(bk, bK[pr] + ks * 32);
                #pragma unroll
                for (int hf = 0; hf < 2; hf++)
                    #pragma unroll
                    for (int mi = 0; mi < 2; mi++) {
                        float* dd = d[mi][pr * 2 + hf];
                        mma16816f(dd, qhf[mi], bk + hf * 2);
                        mma16816f(dd, qlf[mi], bk + hf * 2);
                    }
            }
        }
        #pragma unroll
        for (int mi = 0; mi < 2; mi++)
            #pragma unroll
            for (int nb = 0; nb < 4; nb++)
                #pragma unroll
                for (int j = 0; j < 4; j++) d[mi][nb][j] *= 0.125f;

        // ---- per-row stats ----
        #pragma unroll
        for (int mi = 0; mi < 2; mi++)
        #pragma unroll
        for (int ch = 0; ch < 2; ch++) {
            const int row = wm3 * 32 + mi * 16 + ch * 8 + g;
            float mx = -1e30f, e = 0.f;
            #pragma unroll
            for (int nb = 0; nb < 4; nb++) {
                mx = fmaxf(mx, fmaxf(d[mi][nb][2 * ch], d[mi][nb][2 * ch + 1]));
            }
            mx = fmaxf(mx, __shfl_xor_sync(0xffffffffu, mx, 1));
            mx = fmaxf(mx, __shfl_xor_sync(0xffffffffu, mx, 2));
            #pragma unroll
            for (int nb = 0; nb < 4; nb++)
                e += __expf(d[mi][nb][2 * ch] - mx) + __expf(d[mi][nb][2 * ch + 1] - mx);
            e += __shfl_xor_sync(0xffffffffu, e, 1);
            e += __shfl_xor_sync(0xffffffffu, e, 2);
            if (cc == 0) { pm[row][wn3] = mx; pe[row][wn3] = e; }
        }
        __syncthreads();
        if (tid < 128) {
            const int r2 = tid;
            float m0 = pm[r2][0], m1 = pm[r2][1];
            float mo = ms[r2];
            float mn = fmaxf(mo, fmaxf(m0, m1));
            float scv = __expf(mo - mn);
            ls[r2] = ls[r2] * scv + pe[r2][0] * __expf(m0 - mn) + pe[r2][1] * __expf(m1 - mn);
            ms[r2] = mn; sc[r2] = scv; mc[kt][r2] = mn;
        }
        __syncthreads();

        // ---- u = exp(s-m), store fp16 (global scratch + P smem), rescale O ----
        #pragma unroll
        for (int mi = 0; mi < 2; mi++)
        #pragma unroll
        for (int ch = 0; ch < 2; ch++) {
            const int row = wm3 * 32 + mi * 16 + ch * 8 + g;
            const float mrow = ms[row], scrow = sc[row];
            #pragma unroll
            for (int nb = 0; nb < 4; nb++) {
                float p0 = __expf(d[mi][nb][2 * ch]     - mrow);
                float p1 = __expf(d[mi][nb][2 * ch + 1] - mrow);
                uint32_t w = pack16(p0, p1);
                *(uint32_t*)(ug + (size_t)row * L_ + kt * 64 + wn3 * 32 + nb * 8 + cc * 2) = w;
                s32[WPP + row * SQW + wn3 * 16 + nb * 4 + cc] = w;
                o[mi][nb][2 * ch]     *= scrow;
                o[mi][nb][2 * ch + 1] *= scrow;
            }
        }
        __syncthreads();

        // ---- O += P V (1-term fp16) ----
        uint32_t bV[2];
        #pragma unroll
        for (int pr = 0; pr < 2; pr++)
            bV[pr] = ldmBT_addr(sb + (KVb + 2304) * 4, SQW, wn3 * 32 + pr * 16, lane);
        #pragma unroll
        for (int ks = 0; ks < 4; ks++) {
            uint32_t ap[2][4];
            ldm4(ap[0], aP0 + ks * 32);
            ldm4(ap[1], aP1 + ks * 32);
            #pragma unroll
            for (int pr = 0; pr < 2; pr++) {
                uint32_t bv[4];
                ldm4t(bv, bV[pr] + ks * 16 * SQW * 4);
                #pragma unroll
                for (int hf = 0; hf < 2; hf++)
                    #pragma unroll
                    for (int mi = 0; mi < 2; mi++)
                        mma16816f(o[mi][pr * 2 + hf], ap[mi], bv + hf * 2);
            }
        }
        __syncthreads();
    }

    if (tid < 128) ls[tid] = 1.0f / ls[tid];
    __syncthreads();

    // ---- O epilogue -> g_ahi/g_alo (bf16 hi/lo for out-proj) ----
    #pragma unroll
    for (int mi = 0; mi < 2; mi++)
    #pragma unroll
    for (int nb = 0; nb < 4; nb++)
    #pragma unroll
    for (int ch = 0; ch < 2; ch++) {
        const int row = wm3 * 32 + mi * 16 + ch * 8 + g;
        const int col = wn3 * 32 + nb * 8 + cc * 2;
        const float il = ls[row];
        float v0 = o[mi][nb][2 * ch] * il, v1 = o[mi][nb][2 * ch + 1] * il;
        const size_t base = ((size_t)(b * L_ + q0 + row)) * D_ + h * HD_ + col;
        uint32_t hw = packhl(v0, v1);
        *(uint32_t*)(g_ahi + base) = hw;
        *(uint32_t*)(g_alo + base) = packres(v0, v1, hw);
    }

    // ---- factors f[c][row] = exp(mc - m) * inv_l ----
    for (int i = tid; i < 32 * 128; i += 256) {
        const int c = i >> 7, r2 = i & 127;
        mc[c][r2] = __expf(mc[c][r2] - ms[r2]) * ls[r2];
    }
    __syncthreads();

    // ---- phase 2: A = u * f ----
    for (int i = tid; i < 128 * (L_ / 2); i += 256) {
        const int row = i >> 10;
        const int off = i & 1023;
        const int c = off >> 5;
        __half2 u2 = *(const __half2*)(ug + (size_t)row * L_ + off * 2);
        float f = mc[c][row];
        float2 a = __half22float2(u2);
        *(float2*)(Ar + (size_t)row * L_ + off * 2) = make_float2(a.x * f, a.y * f);
    }
}

extern "C" void kernel_launch(void* const* d_in, const int* in_sizes, int n_in,
                              void* d_out, int out_size) {
    const float* x  = (const float*)d_in[0];
    // d_in[1] = key_indices: unused by the reference computation
    const float* bo = (const float*)d_in[6];
    float* out = (float*)d_out;
    float* A   = out + (size_t)M_ * D_;

    cudaFuncSetAttribute(gemm_mma<1>, cudaFuncAttributeMaxDynamicSharedMemorySize, GSM_BYTES);
    cudaFuncSetAttribute(gemm_mma<0>, cudaFuncAttributeMaxDynamicSharedMemorySize, GSM_BYTES);
    cudaFuncSetAttribute(attn_mma,    cudaFuncAttributeMaxDynamicSharedMemorySize, ASM_BYTES);

    // bf16 hi/lo splits of x and the 4 weights
    split_kernel<<<(M_*D_/4 + 255)/256, 256>>>(x, 0, 0, M_*D_/4);
    for (int z = 0; z < 4; z++)
        split_kernel<<<(D_*D_/4 + 255)/256, 256>>>((const float*)d_in[2 + z], 1, z, D_*D_/4);

    // q,k,v projections (bf16 3-term) -> q fp16 hi/lo, k/v fp16
    gemm_mma<1><<<dim3(8, 64, 3), 256, GSM_BYTES>>>(nullptr, nullptr);

    // flash attention: A + attn output
    attn_mma<<<dim3(16, 16, 4), 256, ASM_BYTES>>>(A);

    // output projection + bias (bf16 3-term)
    gemm_mma<0><<<dim3(8, 64, 1), 256, GSM_BYTES>>>(bo, out);
}

// round 11
// speedup vs baseline: 1.1932x; 1.1932x over previous
#include <cuda_runtime.h>
#include <cuda_bf16.h>
#include <cuda_fp16.h>
#include <cstdint>

#define B_  4
#define L_  2048
#define D_  1024
#define H_  16
#define HD_ 64
#define M_  (B_*L_)   // 8192

// ---------------- scratch (__device__ globals; no allocs allowed) ----------------
__device__ __nv_bfloat16 g_xhi[(size_t)M_*D_], g_xlo[(size_t)M_*D_];
__device__ __nv_bfloat16 g_whi[(size_t)4*D_*D_], g_wlo[(size_t)4*D_*D_];
__device__ __half g_qh16[(size_t)B_*H_*L_*HD_], g_ql16[(size_t)B_*H_*L_*HD_];
__device__ __half g_k16[(size_t)B_*H_*L_*HD_];
__device__ __half g_v16[(size_t)B_*H_*L_*HD_];
__device__ __nv_bfloat16 g_ahi[(size_t)M_*D_], g_alo[(size_t)M_*D_];
__device__ __half g_u[(size_t)B_*H_*L_*L_];   // exp(s - m_running) scratch (fp16)

// ---------------- helpers ----------------
__device__ __forceinline__ uint32_t smem_u32(const void* p) {
    uint32_t a;
    asm("{ .reg .u64 t; cvta.to.shared.u64 t, %1; cvt.u32.u64 %0, t; }" : "=r"(a) : "l"(p));
    return a;
}
__device__ __forceinline__ void cpasync16(uint32_t dst, const void* src) {
    asm volatile("cp.async.cg.shared.global [%0], [%1], 16;" :: "r"(dst), "l"(src));
}
__device__ __forceinline__ void mma16816(float* d, const uint32_t* a, const uint32_t* b) {
    asm volatile(
        "mma.sync.aligned.m16n8k16.row.col.f32.bf16.bf16.f32 "
        "{%0,%1,%2,%3}, {%4,%5,%6,%7}, {%8,%9}, {%0,%1,%2,%3};"
        : "+f"(d[0]), "+f"(d[1]), "+f"(d[2]), "+f"(d[3])
        : "r"(a[0]), "r"(a[1]), "r"(a[2]), "r"(a[3]), "r"(b[0]), "r"(b[1]));
}
__device__ __forceinline__ void mma16816f(float* d, const uint32_t* a, const uint32_t* b) {
    asm volatile(
        "mma.sync.aligned.m16n8k16.row.col.f32.f16.f16.f32 "
        "{%0,%1,%2,%3}, {%4,%5,%6,%7}, {%8,%9}, {%0,%1,%2,%3};"
        : "+f"(d[0]), "+f"(d[1]), "+f"(d[2]), "+f"(d[3])
        : "r"(a[0]), "r"(a[1]), "r"(a[2]), "r"(a[3]), "r"(b[0]), "r"(b[1]));
}
__device__ __forceinline__ void ldm4(uint32_t* r, uint32_t a) {
    asm volatile("ldmatrix.sync.aligned.m8n8.x4.shared.b16 {%0,%1,%2,%3}, [%4];"
        : "=r"(r[0]), "=r"(r[1]), "=r"(r[2]), "=r"(r[3]) : "r"(a));
}
__device__ __forceinline__ void ldm4t(uint32_t* r, uint32_t a) {
    asm volatile("ldmatrix.sync.aligned.m8n8.x4.trans.shared.b16 {%0,%1,%2,%3}, [%4];"
        : "=r"(r[0]), "=r"(r[1]), "=r"(r[2]), "=r"(r[3]) : "r"(a));
}
__device__ __forceinline__ uint32_t ldmA_addr(uint32_t base, int S, int row0, int lane) {
    int lr = lane & 7, sel = lane >> 3;
    return base + (uint32_t)((row0 + lr + (sel & 1) * 8) * S + (sel & 2) * 2) * 4;
}
__device__ __forceinline__ uint32_t ldmB_addr(uint32_t base, int S, int n0, int lane) {
    int lr = lane & 7, sel = lane >> 3;
    return base + (uint32_t)((n0 + lr + (sel >> 1) * 8) * S + (sel & 1) * 4) * 4;
}
__device__ __forceinline__ uint32_t ldmBT_addr(uint32_t base, int S, int n0, int lane) {
    int lr = lane & 7, sel = lane >> 3;
    return base + (uint32_t)((lr + (sel & 1) * 8) * S + (n0 + (sel >> 1) * 8) / 2) * 4;
}
__device__ __forceinline__ uint32_t packhl(float a, float b) {   // bf16 pair
    __nv_bfloat162 t = __halves2bfloat162(__float2bfloat16(a), __float2bfloat16(b));
    return *(uint32_t*)&t;
}
__device__ __forceinline__ uint32_t packres(float a, float b, uint32_t hw) {
    __nv_bfloat162 hv = *(__nv_bfloat162*)&hw;
    return packhl(a - __bfloat162float(hv.x), b - __bfloat162float(hv.y));
}
__device__ __forceinline__ uint32_t pack16(float a, float b) {   // fp16 pair
    __half2 t; t.x = __float2half_rn(a); t.y = __float2half_rn(b);
    return *(uint32_t*)&t;
}
__device__ __forceinline__ uint32_t packres16(float a, float b, uint32_t hw) {
    __half2 hv = *(__half2*)&hw;
    return pack16(a - __half2float(hv.x), b - __half2float(hv.y));
}

// ---------------- fp32 -> bf16 hi/lo split (x and weights) ----------------
__global__ __launch_bounds__(256) void split_kernel(const float* __restrict__ src, int sel, int z, int n4)
{
    int i = blockIdx.x * blockDim.x + threadIdx.x;
    if (i >= n4) return;
    __nv_bfloat16 *hi, *lo;
    if (sel == 0) { hi = g_xhi; lo = g_xlo; }
    else          { hi = g_whi + (size_t)z * D_ * D_; lo = g_wlo + (size_t)z * D_ * D_; }
    float4 v = ((const float4*)src)[i];
    uint32_t h0 = packhl(v.x, v.y), h1 = packhl(v.z, v.w);
    uint32_t l0 = packres(v.x, v.y, h0), l1 = packres(v.z, v.w, h1);
    ((uint32_t*)(hi + 4 * (size_t)i))[0] = h0; ((uint32_t*)(hi + 4 * (size_t)i))[1] = h1;
    ((uint32_t*)(lo + 4 * (size_t)i))[0] = l0; ((uint32_t*)(lo + 4 * (size_t)i))[1] = l1;
}

// ---------------- HMMA GEMM (bf16 3-term): C[m,n] = sum_k X[m,k]*W[n,k] ----------------
#define SRW  36
#define MATW (128*SRW)
#define BUFW (4*MATW)
#define GSM_BYTES (2*BUFW*4)

template<int MODE>
__global__ __launch_bounds__(256) void gemm_mma(const float* __restrict__ bias, float* __restrict__ Out)
{
    extern __shared__ char smch[];
    const uint32_t sb = smem_u32(smch);

    const int tid = threadIdx.x, lane = tid & 31, wid = tid >> 5;
    const int wm = wid & 3, wn = wid >> 2;
    const int g = lane >> 2, cc = lane & 3;
    const int n0 = blockIdx.x * 128, m0 = blockIdx.y * 128;

    const __nv_bfloat16 *Ahp, *Alp, *Whp, *Wlp;
    int z = 0;
    if (MODE == 1) {
        z = blockIdx.z;
        Ahp = g_xhi; Alp = g_xlo;
        Whp = g_whi + (size_t)z * D_ * D_; Wlp = g_wlo + (size_t)z * D_ * D_;
    } else {
        Ahp = g_ahi; Alp = g_alo;
        Whp = g_whi + (size_t)3 * D_ * D_; Wlp = g_wlo + (size_t)3 * D_ * D_;
    }

    const int r = tid >> 1, half = tid & 1;
    const size_t garow = (size_t)(m0 + r) * D_ + half * 32;
    const size_t gbrow = (size_t)(n0 + r) * D_ + half * 32;
    const uint32_t sdst = sb + (uint32_t)(r * SRW + half * 16) * 4;

    auto issue_chunk = [&](int c) {
        const int k0 = c * 64;
        const uint32_t d0 = sdst + (uint32_t)((c & 1) * BUFW) * 4;
        const __nv_bfloat16* pa = Ahp + garow + k0;
        const __nv_bfloat16* pl = Alp + garow + k0;
        const __nv_bfloat16* pb = Whp + gbrow + k0;
        const __nv_bfloat16* pq = Wlp + gbrow + k0;
        #pragma unroll
        for (int j = 0; j < 4; j++) {
            cpasync16(d0 + j * 16,                 pa + j * 8);
            cpasync16(d0 + MATW * 4 + j * 16,      pl + j * 8);
            cpasync16(d0 + 2 * MATW * 4 + j * 16,  pb + j * 8);
            cpasync16(d0 + 3 * MATW * 4 + j * 16,  pq + j * 8);
        }
    };

    float d[2][8][4] = {};

    issue_chunk(0);
    asm volatile("cp.async.commit_group;" ::: "memory");

    for (int c = 0; c < 16; c++) {
        if (c < 15) {
            issue_chunk(c + 1);
            asm volatile("cp.async.commit_group;" ::: "memory");
            asm volatile("cp.async.wait_group 1;" ::: "memory");
        } else {
            asm volatile("cp.async.wait_group 0;" ::: "memory");
        }
        __syncthreads();

        const uint32_t bufb = sb + (uint32_t)((c & 1) * BUFW) * 4;
        const uint32_t aA0 = ldmA_addr(bufb, SRW, wm * 32, lane);
        const uint32_t aA1 = ldmA_addr(bufb, SRW, wm * 32 + 16, lane);
        uint32_t bB[2][2];
        #pragma unroll
        for (int nq = 0; nq < 2; nq++)
            #pragma unroll
            for (int pr = 0; pr < 2; pr++)
                bB[nq][pr] = ldmB_addr(bufb + 2 * MATW * 4, SRW, wn * 64 + nq * 32 + pr * 16, lane);

        #pragma unroll
        for (int ks = 0; ks < 4; ks++) {
            uint32_t ah[2][4], al[2][4];
            ldm4(ah[0], aA0 + ks * 32);
            ldm4(ah[1], aA1 + ks * 32);
            ldm4(al[0], aA0 + MATW * 4 + ks * 32);
            ldm4(al[1], aA1 + MATW * 4 + ks * 32);
            #pragma unroll
            for (int nq = 0; nq < 2; nq++)
                #pragma unroll
                for (int pr = 0; pr < 2; pr++) {
                    uint32_t bhp[4], blp[4];
                    ldm4(bhp, bB[nq][pr] + ks * 32);
                    ldm4(blp, bB[nq][pr] + MATW * 4 + ks * 32);
                    #pragma unroll
                    for (int hf = 0; hf < 2; hf++)
                        #pragma unroll
                        for (int mi = 0; mi < 2; mi++) {
                            float* dd = d[mi][nq * 4 + pr * 2 + hf];
                            mma16816(dd, ah[mi], bhp + hf * 2);
                            mma16816(dd, ah[mi], blp + hf * 2);
                            mma16816(dd, al[mi], bhp + hf * 2);
                        }
                }
        }
        __syncthreads();
    }

    // epilogue
    #pragma unroll
    for (int mi = 0; mi < 2; mi++) {
        const int row = m0 + wm * 32 + mi * 16 + g;
        #pragma unroll
        for (int ni = 0; ni < 8; ni++) {
            const int col = n0 + wn * 64 + ni * 8 + cc * 2;
            float* dd = d[mi][ni];
            if (MODE == 1) {
                int b = row >> 11, l = row & (L_ - 1);
                int hh = col >> 6, dp = col & 63;
                size_t base = ((size_t)(b * H_ + hh) * L_ + l) * HD_ + dp;
                uint32_t h0 = pack16(dd[0], dd[1]), h1 = pack16(dd[2], dd[3]);
                if (z == 0) {
                    *(uint32_t*)(g_qh16 + base)           = h0;
                    *(uint32_t*)(g_qh16 + base + 8 * HD_) = h1;
                    *(uint32_t*)(g_ql16 + base)           = packres16(dd[0], dd[1], h0);
                    *(uint32_t*)(g_ql16 + base + 8 * HD_) = packres16(dd[2], dd[3], h1);
                } else {
                    __half* dst = (z == 1) ? g_k16 : g_v16;
                    *(uint32_t*)(dst + base)           = h0;
                    *(uint32_t*)(dst + base + 8 * HD_) = h1;
                }
            } else {
                float bx = bias[col], by = bias[col + 1];
                *(float2*)(Out + (size_t)row * D_ + col) =
                    make_float2(dd[0] + bx, dd[1] + by);
                *(float2*)(Out + (size_t)(row + 8) * D_ + col) =
                    make_float2(dd[2] + bx, dd[3] + by);
            }
        }
    }
}

// ---------------- two-phase tensor-core attention (fp16, u scratch) ----------------
// CTA = (b, h, 64 q-rows), 16 chunks of 128 keys.
// Phase 1: S = Q K^T (fp16 2-term), u = exp(s - m_run) -> fp16 global, mc[kt] recorded.
// Phase 2: p = u * exp(mc - m)/l (factor precomputed), A written, P fp16 -> PV 1-term.
#define SQW  36
#define WQLO 2304
#define WKV  4608             // K/V double buffer: 2 x 4608 words
#define WPP  13824            // P: 64 x 68 words
#define SPW  68
#define ASM_BYTES (18176*4)   // 72704

__global__ __launch_bounds__(256) void attn_mma(float* __restrict__ A)
{
    extern __shared__ uint32_t s32[];
    __shared__ float ms[64], ls[64], pm[64][4], pe[64][4];
    __shared__ float fc[16][64];

    const int tid = threadIdx.x, lane = tid & 31, wid = tid >> 5;
    const int g = lane >> 2, cc = lane & 3;
    const int wm = wid & 1,  wn = wid >> 1;    // phase 1: 2m x 4n
    const int wm2 = wid & 3, wn2 = wid >> 2;   // phase 2: 4m x 2n
    const int q0 = blockIdx.x * 64, h = blockIdx.y, b = blockIdx.z;
    const int bh = b * H_ + h;
    const __half* qh = g_qh16 + (size_t)bh * L_ * HD_;
    const __half* ql = g_ql16 + (size_t)bh * L_ * HD_;
    const __half* kp = g_k16  + (size_t)bh * L_ * HD_;
    const __half* vp = g_v16  + (size_t)bh * L_ * HD_;
    __half* ug = g_u + ((size_t)bh * L_ + q0) * L_;
    float* Ar = A + ((size_t)bh * L_ + q0) * L_;
    const uint32_t sb = smem_u32(s32);

    // Q 64x64 hi/lo fp16 -> smem
    {
        const int r = tid >> 2, qseg = tid & 3;
        #pragma unroll
        for (int j = 0; j < 2; j++) {
            const int s0 = qseg * 2 + j;
            *(uint4*)&s32[r * SQW + s0 * 4]        = *(const uint4*)(qh + (size_t)(q0 + r) * HD_ + s0 * 8);
            *(uint4*)&s32[WQLO + r * SQW + s0 * 4] = *(const uint4*)(ql + (size_t)(q0 + r) * HD_ + s0 * 8);
        }
    }
    if (tid < 64) { ms[tid] = -1e30f; ls[tid] = 0.f; }

    auto loadK = [&](int kt) {
        const int r = tid >> 1, half = tid & 1;
        const uint32_t bo = WKV + (kt & 1) * 4608;
        const __half* src = kp + (size_t)(kt * 128 + r) * HD_ + half * 32;
        const uint32_t dst = sb + (bo + r * SQW + half * 16) * 4;
        #pragma unroll
        for (int j = 0; j < 4; j++) cpasync16(dst + j * 16, src + j * 8);
    };
    auto loadV = [&](int kt) {
        const int r = tid >> 1, half = tid & 1;
        const uint32_t bo = WKV + (kt & 1) * 4608;
        const __half* src = vp + (size_t)(kt * 128 + r) * HD_ + half * 32;
        const uint32_t dst = sb + (bo + r * SQW + half * 16) * 4;
        #pragma unroll
        for (int j = 0; j < 4; j++) cpasync16(dst + j * 16, src + j * 8);
    };

    loadK(0);
    asm volatile("cp.async.commit_group;" ::: "memory");

    const uint32_t aQh0 = ldmA_addr(sb, SQW, wm * 32, lane);
    const uint32_t aQh1 = ldmA_addr(sb, SQW, wm * 32 + 16, lane);

    // ---------------- phase 1 ----------------
    for (int kt = 0; kt < 16; kt++) {
        if (kt < 15) {
            loadK(kt + 1);
            asm volatile("cp.async.commit_group;" ::: "memory");
            asm volatile("cp.async.wait_group 1;" ::: "memory");
        } else {
            asm volatile("cp.async.wait_group 0;" ::: "memory");
        }
        __syncthreads();

        const uint32_t Kb = sb + (WKV + (kt & 1) * 4608) * 4;
        uint32_t bK[2];
        #pragma unroll
        for (int pr = 0; pr < 2; pr++)
            bK[pr] = ldmB_addr(Kb, SQW, wn * 32 + pr * 16, lane);

        float d[2][4][4] = {};
        #pragma unroll
        for (int ks = 0; ks < 4; ks++) {
            uint32_t qhf[2][4], qlf[2][4];
            ldm4(qhf[0], aQh0 + ks * 32);
            ldm4(qhf[1], aQh1 + ks * 32);
            ldm4(qlf[0], aQh0 + WQLO * 4 + ks * 32);
            ldm4(qlf[1], aQh1 + WQLO * 4 + ks * 32);
            #pragma unroll
            for (int pr = 0; pr < 2; pr++) {
                uint32_t bk[4];
                ldm4(bk, bK[pr] + ks * 32);
                #pragma unroll
                for (int hf = 0; hf < 2; hf++)
                    #pragma unroll
                    for (int mi = 0; mi < 2; mi++) {
                        float* dd = d[mi][pr * 2 + hf];
                        mma16816f(dd, qhf[mi], bk + hf * 2);
                        mma16816f(dd, qlf[mi], bk + hf * 2);
                    }
            }
        }
        #pragma unroll
        for (int mi = 0; mi < 2; mi++)
            #pragma unroll
            for (int nb = 0; nb < 4; nb++)
                #pragma unroll
                for (int j = 0; j < 4; j++) d[mi][nb][j] *= 0.125f;

        // per-row chunk stats
        #pragma unroll
        for (int mi = 0; mi < 2; mi++)
        #pragma unroll
        for (int ch = 0; ch < 2; ch++) {
            const int row = wm * 32 + mi * 16 + ch * 8 + g;
            float mx = -1e30f, e = 0.f;
            #pragma unroll
            for (int nb = 0; nb < 4; nb++)
                mx = fmaxf(mx, fmaxf(d[mi][nb][2 * ch], d[mi][nb][2 * ch + 1]));
            mx = fmaxf(mx, __shfl_xor_sync(0xffffffffu, mx, 1));
            mx = fmaxf(mx, __shfl_xor_sync(0xffffffffu, mx, 2));
            #pragma unroll
            for (int nb = 0; nb < 4; nb++)
                e += __expf(d[mi][nb][2 * ch] - mx) + __expf(d[mi][nb][2 * ch + 1] - mx);
            e += __shfl_xor_sync(0xffffffffu, e, 1);
            e += __shfl_xor_sync(0xffffffffu, e, 2);
            if (cc == 0) { pm[row][wn] = mx; pe[row][wn] = e; }
        }
        __syncthreads();
        if (tid < 64) {
            float mo = ms[tid], lo = ls[tid];
            float mn = mo;
            #pragma unroll
            for (int w = 0; w < 4; w++) mn = fmaxf(mn, pm[tid][w]);
            lo *= __expf(mo - mn);
            #pragma unroll
            for (int w = 0; w < 4; w++) lo += pe[tid][w] * __expf(pm[tid][w] - mn);
            ms[tid] = mn; ls[tid] = lo; fc[kt][tid] = mn;
        }
        __syncthreads();

        // u = exp(s - m_run) -> fp16 global
        #pragma unroll
        for (int mi = 0; mi < 2; mi++)
        #pragma unroll
        for (int ch = 0; ch < 2; ch++) {
            const int row = wm * 32 + mi * 16 + ch * 8 + g;
            const float mrow = ms[row];
            #pragma unroll
            for (int nb = 0; nb < 4; nb++) {
                float p0 = __expf(d[mi][nb][2 * ch]     - mrow);
                float p1 = __expf(d[mi][nb][2 * ch + 1] - mrow);
                *(uint32_t*)(ug + (size_t)row * L_ + kt * 128 + wn * 32 + nb * 8 + cc * 2)
                    = pack16(p0, p1);
            }
        }
    }

    __syncthreads();
    if (tid < 64) ls[tid] = 1.0f / ls[tid];
    loadV(0);
    asm volatile("cp.async.commit_group;" ::: "memory");
    __syncthreads();
    // fc[kt][row] = exp(mc - m_final) * inv_l
    for (int i = tid; i < 16 * 64; i += 256) {
        const int c = i >> 6, r2 = i & 63;
        fc[c][r2] = __expf(fc[c][r2] - ms[r2]) * ls[r2];
    }
    __syncthreads();

    // ---------------- phase 2 ----------------
    const uint32_t aP = ldmA_addr(sb + WPP * 4, SPW, wm2 * 16, lane);
    float o[4][4] = {};

    for (int kt = 0; kt < 16; kt++) {
        if (kt < 15) {
            loadV(kt + 1);
            asm volatile("cp.async.commit_group;" ::: "memory");
        }
        // build P: read u (L2-hot), p = u*f, write final A, stage P fp16
        #pragma unroll
        for (int mi = 0; mi < 2; mi++)
        #pragma unroll
        for (int ch = 0; ch < 2; ch++) {
            const int row = wm * 32 + mi * 16 + ch * 8 + g;
            const float f = fc[kt][row];
            #pragma unroll
            for (int nb = 0; nb < 4; nb++) {
                const int col = kt * 128 + wn * 32 + nb * 8 + cc * 2;
                __half2 u2 = *(const __half2*)(ug + (size_t)row * L_ + col);
                float2 uf = __half22float2(u2);
                float p0 = uf.x * f, p1 = uf.y * f;
                *(float2*)(Ar + (size_t)row * L_ + col) = make_float2(p0, p1);
                s32[WPP + row * SPW + wn * 16 + nb * 4 + cc] = pack16(p0, p1);
            }
        }
        if (kt < 15) asm volatile("cp.async.wait_group 1;" ::: "memory");
        else         asm volatile("cp.async.wait_group 0;" ::: "memory");
        __syncthreads();   // V(kt) visible + P staged

        const uint32_t Vb = sb + (WKV + (kt & 1) * 4608) * 4;
        uint32_t bV[2];
        #pragma unroll
        for (int np = 0; np < 2; np++)
            bV[np] = ldmBT_addr(Vb, SQW, wn2 * 32 + np * 16, lane);

        #pragma unroll
        for (int ks = 0; ks < 8; ks++) {
            uint32_t ap[4];
            ldm4(ap, aP + ks * 32);
            #pragma unroll
            for (int np = 0; np < 2; np++) {
                uint32_t bv[4];
                ldm4t(bv, bV[np] + ks * 16 * SQW * 4);
                #pragma unroll
                for (int hf = 0; hf < 2; hf++)
                    mma16816f(o[np * 2 + hf], ap, bv + hf * 2);
            }
        }
        __syncthreads();   // protect V dbuf + P before next chunk
    }

    // epilogue: O (final, P already normalized) -> g_ahi/g_alo
    #pragma unroll
    for (int nn = 0; nn < 4; nn++)
    #pragma unroll
    for (int ch = 0; ch < 2; ch++) {
        const int row = wm2 * 16 + ch * 8 + g;
        const int col = wn2 * 32 + nn * 8 + cc * 2;
        const size_t base = ((size_t)(b * L_ + q0 + row)) * D_ + h * HD_ + col;
        float v0 = o[nn][2 * ch], v1 = o[nn][2 * ch + 1];
        uint32_t hw = packhl(v0, v1);
        *(uint32_t*)(g_ahi + base) = hw;
        *(uint32_t*)(g_alo + base) = packres(v0, v1, hw);
    }
}

extern "C" void kernel_launch(void* const* d_in, const int* in_sizes, int n_in,
                              void* d_out, int out_size) {
    const float* x  = (const float*)d_in[0];
    // d_in[1] = key_indices: unused by the reference computation
    const float* bo = (const float*)d_in[6];
    float* out = (float*)d_out;
    float* A   = out + (size_t)M_ * D_;

    cudaFuncSetAttribute(gemm_mma<1>, cudaFuncAttributeMaxDynamicSharedMemorySize, GSM_BYTES);
    cudaFuncSetAttribute(gemm_mma<0>, cudaFuncAttributeMaxDynamicSharedMemorySize, GSM_BYTES);
    cudaFuncSetAttribute(attn_mma,    cudaFuncAttributeMaxDynamicSharedMemorySize, ASM_BYTES);

    // bf16 hi/lo splits of x and the 4 weights
    split_kernel<<<(M_*D_/4 + 255)/256, 256>>>(x, 0, 0, M_*D_/4);
    for (int z = 0; z < 4; z++)
        split_kernel<<<(D_*D_/4 + 255)/256, 256>>>((const float*)d_in[2 + z], 1, z, D_*D_/4);

    // q,k,v projections (bf16 3-term) -> q fp16 hi/lo, k/v fp16
    gemm_mma<1><<<dim3(8, 64, 3), 256, GSM_BYTES>>>(nullptr, nullptr);

    // two-phase attention: A + attn output
    attn_mma<<<dim3(32, 16, 4), 256, ASM_BYTES>>>(A);

    // output projection + bias (bf16 3-term)
    gemm_mma<0><<<dim3(8, 64, 1), 256, GSM_BYTES>>>(bo, out);
}

// round 13
// speedup vs baseline: 1.2943x; 1.0848x over previous
#include <cuda_runtime.h>
#include <cuda_bf16.h>
#include <cuda_fp16.h>
#include <cstdint>

#define B_  4
#define L_  2048
#define D_  1024
#define H_  16
#define HD_ 64
#define M_  (B_*L_)   // 8192

// ---------------- scratch (__device__ globals; no allocs allowed) ----------------
__device__ __nv_bfloat16 g_xhi[(size_t)M_*D_], g_xlo[(size_t)M_*D_];
__device__ __nv_bfloat16 g_whi[(size_t)4*D_*D_], g_wlo[(size_t)4*D_*D_];
__device__ __half g_q16[(size_t)B_*H_*L_*HD_];   // pre-scaled by 0.125
__device__ __half g_k16[(size_t)B_*H_*L_*HD_];
__device__ __half g_v16[(size_t)B_*H_*L_*HD_];
__device__ __nv_bfloat16 g_ahi[(size_t)M_*D_], g_alo[(size_t)M_*D_];
__device__ __half g_u[(size_t)B_*H_*L_*L_];   // exp(s - m_running) scratch (fp16)

// ---------------- helpers ----------------
__device__ __forceinline__ uint32_t smem_u32(const void* p) {
    uint32_t a;
    asm("{ .reg .u64 t; cvta.to.shared.u64 t, %1; cvt.u32.u64 %0, t; }" : "=r"(a) : "l"(p));
    return a;
}
__device__ __forceinline__ void cpasync16(uint32_t dst, const void* src) {
    asm volatile("cp.async.cg.shared.global [%0], [%1], 16;" :: "r"(dst), "l"(src));
}
__device__ __forceinline__ void mma16816(float* d, const uint32_t* a, const uint32_t* b) {
    asm volatile(
        "mma.sync.aligned.m16n8k16.row.col.f32.bf16.bf16.f32 "
        "{%0,%1,%2,%3}, {%4,%5,%6,%7}, {%8,%9}, {%0,%1,%2,%3};"
        : "+f"(d[0]), "+f"(d[1]), "+f"(d[2]), "+f"(d[3])
        : "r"(a[0]), "r"(a[1]), "r"(a[2]), "r"(a[3]), "r"(b[0]), "r"(b[1]));
}
__device__ __forceinline__ void mma16816f(float* d, const uint32_t* a, const uint32_t* b) {
    asm volatile(
        "mma.sync.aligned.m16n8k16.row.col.f32.f16.f16.f32 "
        "{%0,%1,%2,%3}, {%4,%5,%6,%7}, {%8,%9}, {%0,%1,%2,%3};"
        : "+f"(d[0]), "+f"(d[1]), "+f"(d[2]), "+f"(d[3])
        : "r"(a[0]), "r"(a[1]), "r"(a[2]), "r"(a[3]), "r"(b[0]), "r"(b[1]));
}
__device__ __forceinline__ void ldm4(uint32_t* r, uint32_t a) {
    asm volatile("ldmatrix.sync.aligned.m8n8.x4.shared.b16 {%0,%1,%2,%3}, [%4];"
        : "=r"(r[0]), "=r"(r[1]), "=r"(r[2]), "=r"(r[3]) : "r"(a));
}
__device__ __forceinline__ void ldm4t(uint32_t* r, uint32_t a) {
    asm volatile("ldmatrix.sync.aligned.m8n8.x4.trans.shared.b16 {%0,%1,%2,%3}, [%4];"
        : "=r"(r[0]), "=r"(r[1]), "=r"(r[2]), "=r"(r[3]) : "r"(a));
}
__device__ __forceinline__ uint32_t ldmA_addr(uint32_t base, int S, int row0, int lane) {
    int lr = lane & 7, sel = lane >> 3;
    return base + (uint32_t)((row0 + lr + (sel & 1) * 8) * S + (sel & 2) * 2) * 4;
}
__device__ __forceinline__ uint32_t ldmB_addr(uint32_t base, int S, int n0, int lane) {
    int lr = lane & 7, sel = lane >> 3;
    return base + (uint32_t)((n0 + lr + (sel >> 1) * 8) * S + (sel & 1) * 4) * 4;
}
__device__ __forceinline__ uint32_t ldmBT_addr(uint32_t base, int S, int n0, int lane) {
    int lr = lane & 7, sel = lane >> 3;
    return base + (uint32_t)((lr + (sel & 1) * 8) * S + (n0 + (sel >> 1) * 8) / 2) * 4;
}
__device__ __forceinline__ uint32_t packhl(float a, float b) {   // bf16 pair
    __nv_bfloat162 t = __halves2bfloat162(__float2bfloat16(a), __float2bfloat16(b));
    return *(uint32_t*)&t;
}
__device__ __forceinline__ uint32_t packres(float a, float b, uint32_t hw) {
    __nv_bfloat162 hv = *(__nv_bfloat162*)&hw;
    return packhl(a - __bfloat162float(hv.x), b - __bfloat162float(hv.y));
}
__device__ __forceinline__ uint32_t pack16(float a, float b) {   // fp16 pair
    __half2 t; t.x = __float2half_rn(a); t.y = __float2half_rn(b);
    return *(uint32_t*)&t;
}

// ---------------- fp32 -> bf16 hi/lo split (x and weights) ----------------
__global__ __launch_bounds__(256) void split_kernel(const float* __restrict__ src, int sel, int z, int n4)
{
    int i = blockIdx.x * blockDim.x + threadIdx.x;
    if (i >= n4) return;
    __nv_bfloat16 *hi, *lo;
    if (sel == 0) { hi = g_xhi; lo = g_xlo; }
    else          { hi = g_whi + (size_t)z * D_ * D_; lo = g_wlo + (size_t)z * D_ * D_; }
    float4 v = ((const float4*)src)[i];
    uint32_t h0 = packhl(v.x, v.y), h1 = packhl(v.z, v.w);
    uint32_t l0 = packres(v.x, v.y, h0), l1 = packres(v.z, v.w, h1);
    ((uint32_t*)(hi + 4 * (size_t)i))[0] = h0; ((uint32_t*)(hi + 4 * (size_t)i))[1] = h1;
    ((uint32_t*)(lo + 4 * (size_t)i))[0] = l0; ((uint32_t*)(lo + 4 * (size_t)i))[1] = l1;
}

// ---------------- HMMA GEMM (bf16 3-term): C[m,n] = sum_k X[m,k]*W[n,k] ----------------
#define SRW  36
#define MATW (128*SRW)
#define BUFW (4*MATW)
#define GSM_BYTES (2*BUFW*4)

template<int MODE>
__global__ __launch_bounds__(256) void gemm_mma(const float* __restrict__ bias, float* __restrict__ Out)
{
    extern __shared__ char smch[];
    const uint32_t sb = smem_u32(smch);

    const int tid = threadIdx.x, lane = tid & 31, wid = tid >> 5;
    const int wm = wid & 3, wn = wid >> 2;
    const int g = lane >> 2, cc = lane & 3;
    const int n0 = blockIdx.x * 128, m0 = blockIdx.y * 128;

    const __nv_bfloat16 *Ahp, *Alp, *Whp, *Wlp;
    int z = 0;
    if (MODE == 1) {
        z = blockIdx.z;
        Ahp = g_xhi; Alp = g_xlo;
        Whp = g_whi + (size_t)z * D_ * D_; Wlp = g_wlo + (size_t)z * D_ * D_;
    } else {
        Ahp = g_ahi; Alp = g_alo;
        Whp = g_whi + (size_t)3 * D_ * D_; Wlp = g_wlo + (size_t)3 * D_ * D_;
    }

    const int r = tid >> 1, half = tid & 1;
    const size_t garow = (size_t)(m0 + r) * D_ + half * 32;
    const size_t gbrow = (size_t)(n0 + r) * D_ + half * 32;
    const uint32_t sdst = sb + (uint32_t)(r * SRW + half * 16) * 4;

    auto issue_chunk = [&](int c) {
        const int k0 = c * 64;
        const uint32_t d0 = sdst + (uint32_t)((c & 1) * BUFW) * 4;
        const __nv_bfloat16* pa = Ahp + garow + k0;
        const __nv_bfloat16* pl = Alp + garow + k0;
        const __nv_bfloat16* pb = Whp + gbrow + k0;
        const __nv_bfloat16* pq = Wlp + gbrow + k0;
        #pragma unroll
        for (int j = 0; j < 4; j++) {
            cpasync16(d0 + j * 16,                 pa + j * 8);
            cpasync16(d0 + MATW * 4 + j * 16,      pl + j * 8);
            cpasync16(d0 + 2 * MATW * 4 + j * 16,  pb + j * 8);
            cpasync16(d0 + 3 * MATW * 4 + j * 16,  pq + j * 8);
        }
    };

    float d[2][8][4] = {};

    issue_chunk(0);
    asm volatile("cp.async.commit_group;" ::: "memory");

    for (int c = 0; c < 16; c++) {
        if (c < 15) {
            issue_chunk(c + 1);
            asm volatile("cp.async.commit_group;" ::: "memory");
            asm volatile("cp.async.wait_group 1;" ::: "memory");
        } else {
            asm volatile("cp.async.wait_group 0;" ::: "memory");
        }
        __syncthreads();

        const uint32_t bufb = sb + (uint32_t)((c & 1) * BUFW) * 4;
        const uint32_t aA0 = ldmA_addr(bufb, SRW, wm * 32, lane);
        const uint32_t aA1 = ldmA_addr(bufb, SRW, wm * 32 + 16, lane);
        uint32_t bB[2][2];
        #pragma unroll
        for (int nq = 0; nq < 2; nq++)
            #pragma unroll
            for (int pr = 0; pr < 2; pr++)
                bB[nq][pr] = ldmB_addr(bufb + 2 * MATW * 4, SRW, wn * 64 + nq * 32 + pr * 16, lane);

        #pragma unroll
        for (int ks = 0; ks < 4; ks++) {
            uint32_t ah[2][4], al[2][4];
            ldm4(ah[0], aA0 + ks * 32);
            ldm4(ah[1], aA1 + ks * 32);
            ldm4(al[0], aA0 + MATW * 4 + ks * 32);
            ldm4(al[1], aA1 + MATW * 4 + ks * 32);
            #pragma unroll
            for (int nq = 0; nq < 2; nq++)
                #pragma unroll
                for (int pr = 0; pr < 2; pr++) {
                    uint32_t bhp[4], blp[4];
                    ldm4(bhp, bB[nq][pr] + ks * 32);
                    ldm4(blp, bB[nq][pr] + MATW * 4 + ks * 32);
                    #pragma unroll
                    for (int hf = 0; hf < 2; hf++)
                        #pragma unroll
                        for (int mi = 0; mi < 2; mi++) {
                            float* dd = d[mi][nq * 4 + pr * 2 + hf];
                            mma16816(dd, ah[mi], bhp + hf * 2);
                            mma16816(dd, ah[mi], blp + hf * 2);
                            mma16816(dd, al[mi], bhp + hf * 2);
                        }
                }
        }
        __syncthreads();
    }

    // epilogue
    #pragma unroll
    for (int mi = 0; mi < 2; mi++) {
        const int row = m0 + wm * 32 + mi * 16 + g;
        #pragma unroll
        for (int ni = 0; ni < 8; ni++) {
            const int col = n0 + wn * 64 + ni * 8 + cc * 2;
            float* dd = d[mi][ni];
            if (MODE == 1) {
                int b = row >> 11, l = row & (L_ - 1);
                int hh = col >> 6, dp = col & 63;
                size_t base = ((size_t)(b * H_ + hh) * L_ + l) * HD_ + dp;
                if (z == 0) {
                    // store q pre-scaled by 1/8 (score scale folded in)
                    *(uint32_t*)(g_q16 + base)           = pack16(dd[0] * 0.125f, dd[1] * 0.125f);
                    *(uint32_t*)(g_q16 + base + 8 * HD_) = pack16(dd[2] * 0.125f, dd[3] * 0.125f);
                } else {
                    __half* dst = (z == 1) ? g_k16 : g_v16;
                    *(uint32_t*)(dst + base)           = pack16(dd[0], dd[1]);
                    *(uint32_t*)(dst + base + 8 * HD_) = pack16(dd[2], dd[3]);
                }
            } else {
                float bx = bias[col], by = bias[col + 1];
                *(float2*)(Out + (size_t)row * D_ + col) =
                    make_float2(dd[0] + bx, dd[1] + by);
                *(float2*)(Out + (size_t)(row + 8) * D_ + col) =
                    make_float2(dd[2] + bx, dd[3] + by);
            }
        }
    }
}

// ---------------- two-phase tensor-core attention (fp16 1-term, u scratch) ----------------
// CTA = (b, h, 64 q-rows), 16 chunks of 128 keys.
// Phase 1: S = Q K^T (fp16 1-term, q pre-scaled), u = exp(s - m_run) -> fp16 global.
// Phase 2: p = u * exp(mc - m)/l, A written, P fp16 -> PV 1-term.
#define SQW  36
#define WKV  2304             // K/V double buffer: 2 x 4608 words
#define WPP  11520            // P: 64 x 68 words
#define SPW  68
#define ASM_BYTES (15872*4)   // 63488

__global__ __launch_bounds__(256) void attn_mma(float* __restrict__ A)
{
    extern __shared__ uint32_t s32[];
    __shared__ float ms[64], ls[64], pm[64][4], pe[64][4];
    __shared__ float fc[16][64];

    const int tid = threadIdx.x, lane = tid & 31, wid = tid >> 5;
    const int g = lane >> 2, cc = lane & 3;
    const int wm = wid & 1,  wn = wid >> 1;    // phase 1: 2m x 4n
    const int wm2 = wid & 3, wn2 = wid >> 2;   // phase 2: 4m x 2n
    const int q0 = blockIdx.x * 64, h = blockIdx.y, b = blockIdx.z;
    const int bh = b * H_ + h;
    const __half* qp = g_q16 + (size_t)bh * L_ * HD_;
    const __half* kp = g_k16 + (size_t)bh * L_ * HD_;
    const __half* vp = g_v16 + (size_t)bh * L_ * HD_;
    __half* ug = g_u + ((size_t)bh * L_ + q0) * L_;
    float* Ar = A + ((size_t)bh * L_ + q0) * L_;
    const uint32_t sb = smem_u32(s32);

    // Q 64x64 fp16 -> smem
    {
        const int r = tid >> 2, qseg = tid & 3;
        #pragma unroll
        for (int j = 0; j < 2; j++) {
            const int s0 = qseg * 2 + j;
            *(uint4*)&s32[r * SQW + s0 * 4] = *(const uint4*)(qp + (size_t)(q0 + r) * HD_ + s0 * 8);
        }
    }
    if (tid < 64) { ms[tid] = -1e30f; ls[tid] = 0.f; }

    auto loadK = [&](int kt) {
        const int r = tid >> 1, half = tid & 1;
        const uint32_t bo = WKV + (kt & 1) * 4608;
        const __half* src = kp + (size_t)(kt * 128 + r) * HD_ + half * 32;
        const uint32_t dst = sb + (bo + r * SQW + half * 16) * 4;
        #pragma unroll
        for (int j = 0; j < 4; j++) cpasync16(dst + j * 16, src + j * 8);
    };
    auto loadV = [&](int kt) {
        const int r = tid >> 1, half = tid & 1;
        const uint32_t bo = WKV + (kt & 1) * 4608;
        const __half* src = vp + (size_t)(kt * 128 + r) * HD_ + half * 32;
        const uint32_t dst = sb + (bo + r * SQW + half * 16) * 4;
        #pragma unroll
        for (int j = 0; j < 4; j++) cpasync16(dst + j * 16, src + j * 8);
    };

    loadK(0);
    asm volatile("cp.async.commit_group;" ::: "memory");

    const uint32_t aQ0 = ldmA_addr(sb, SQW, wm * 32, lane);
    const uint32_t aQ1 = ldmA_addr(sb, SQW, wm * 32 + 16, lane);

    // ---------------- phase 1 ----------------
    for (int kt = 0; kt < 16; kt++) {
        if (kt < 15) {
            loadK(kt + 1);
            asm volatile("cp.async.commit_group;" ::: "memory");
            asm volatile("cp.async.wait_group 1;" ::: "memory");
        } else {
            asm volatile("cp.async.wait_group 0;" ::: "memory");
        }
        __syncthreads();

        const uint32_t Kb = sb + (WKV + (kt & 1) * 4608) * 4;
        uint32_t bK[2];
        #pragma unroll
        for (int pr = 0; pr < 2; pr++)
            bK[pr] = ldmB_addr(Kb, SQW, wn * 32 + pr * 16, lane);

        float d[2][4][4] = {};
        #pragma unroll
        for (int ks = 0; ks < 4; ks++) {
            uint32_t qf[2][4];
            ldm4(qf[0], aQ0 + ks * 32);
            ldm4(qf[1], aQ1 + ks * 32);
            #pragma unroll
            for (int pr = 0; pr < 2; pr++) {
                uint32_t bk[4];
                ldm4(bk, bK[pr] + ks * 32);
                #pragma unroll
                for (int hf = 0; hf < 2; hf++)
                    #pragma unroll
                    for (int mi = 0; mi < 2; mi++)
                        mma16816f(d[mi][pr * 2 + hf], qf[mi], bk + hf * 2);
            }
        }

        // per-row chunk stats (scores already scaled via q)
        #pragma unroll
        for (int mi = 0; mi < 2; mi++)
        #pragma unroll
        for (int ch = 0; ch < 2; ch++) {
            const int row = wm * 32 + mi * 16 + ch * 8 + g;
            float mx = -1e30f, e = 0.f;
            #pragma unroll
            for (int nb = 0; nb < 4; nb++)
                mx = fmaxf(mx, fmaxf(d[mi][nb][2 * ch], d[mi][nb][2 * ch + 1]));
            mx = fmaxf(mx, __shfl_xor_sync(0xffffffffu, mx, 1));
            mx = fmaxf(mx, __shfl_xor_sync(0xffffffffu, mx, 2));
            #pragma unroll
            for (int nb = 0; nb < 4; nb++)
                e += __expf(d[mi][nb][2 * ch] - mx) + __expf(d[mi][nb][2 * ch + 1] - mx);
            e += __shfl_xor_sync(0xffffffffu, e, 1);
            e += __shfl_xor_sync(0xffffffffu, e, 2);
            if (cc == 0) { pm[row][wn] = mx; pe[row][wn] = e; }
        }
        __syncthreads();
        if (tid < 64) {
            float mo = ms[tid], lo = ls[tid];
            float mn = mo;
            #pragma unroll
            for (int w = 0; w < 4; w++) mn = fmaxf(mn, pm[tid][w]);
            lo *= __expf(mo - mn);
            #pragma unroll
            for (int w = 0; w < 4; w++) lo += pe[tid][w] * __expf(pm[tid][w] - mn);
            ms[tid] = mn; ls[tid] = lo; fc[kt][tid] = mn;
        }
        __syncthreads();

        // u = exp(s - m_run) -> fp16 global
        #pragma unroll
        for (int mi = 0; mi < 2; mi++)
        #pragma unroll
        for (int ch = 0; ch < 2; ch++) {
            const int row = wm * 32 + mi * 16 + ch * 8 + g;
            const float mrow = ms[row];
            #pragma unroll
            for (int nb = 0; nb < 4; nb++) {
                float p0 = __expf(d[mi][nb][2 * ch]     - mrow);
                float p1 = __expf(d[mi][nb][2 * ch + 1] - mrow);
                *(uint32_t*)(ug + (size_t)row * L_ + kt * 128 + wn * 32 + nb * 8 + cc * 2)
                    = pack16(p0, p1);
            }
        }
    }

    __syncthreads();
    if (tid < 64) ls[tid] = 1.0f / ls[tid];
    loadV(0);
    asm volatile("cp.async.commit_group;" ::: "memory");
    __syncthreads();
    // fc[kt][row] = exp(mc - m_final) * inv_l
    for (int i = tid; i < 16 * 64; i += 256) {
        const int c = i >> 6, r2 = i & 63;
        fc[c][r2] = __expf(fc[c][r2] - ms[r2]) * ls[r2];
    }
    __syncthreads();

    // ---------------- phase 2 ----------------
    const uint32_t aP = ldmA_addr(sb + WPP * 4, SPW, wm2 * 16, lane);
    float o[4][4] = {};

    for (int kt = 0; kt < 16; kt++) {
        if (kt < 15) {
            loadV(kt + 1);
            asm volatile("cp.async.commit_group;" ::: "memory");
        }
        // build P: read u (L2-hot), p = u*f, write final A, stage P fp16
        #pragma unroll
        for (int mi = 0; mi < 2; mi++)
        #pragma unroll
        for (int ch = 0; ch < 2; ch++) {
            const int row = wm * 32 + mi * 16 + ch * 8 + g;
            const float f = fc[kt][row];
            #pragma unroll
            for (int nb = 0; nb < 4; nb++) {
                const int col = kt * 128 + wn * 32 + nb * 8 + cc * 2;
                __half2 u2 = *(const __half2*)(ug + (size_t)row * L_ + col);
                float2 uf = __half22float2(u2);
                float p0 = uf.x * f, p1 = uf.y * f;
                *(float2*)(Ar + (size_t)row * L_ + col) = make_float2(p0, p1);
                s32[WPP + row * SPW + wn * 16 + nb * 4 + cc] = pack16(p0, p1);
            }
        }
        if (kt < 15) asm volatile("cp.async.wait_group 1;" ::: "memory");
        else         asm volatile("cp.async.wait_group 0;" ::: "memory");
        __syncthreads();   // V(kt) visible + P staged

        const uint32_t Vb = sb + (WKV + (kt & 1) * 4608) * 4;
        uint32_t bV[2];
        #pragma unroll
        for (int np = 0; np < 2; np++)
            bV[np] = ldmBT_addr(Vb, SQW, wn2 * 32 + np * 16, lane);

        #pragma unroll
        for (int ks = 0; ks < 8; ks++) {
            uint32_t ap[4];
            ldm4(ap, aP + ks * 32);
            #pragma unroll
            for (int np = 0; np < 2; np++) {
                uint32_t bv[4];
                ldm4t(bv, bV[np] + ks * 16 * SQW * 4);
                #pragma unroll
                for (int hf = 0; hf < 2; hf++)
                    mma16816f(o[np * 2 + hf], ap, bv + hf * 2);
            }
        }
        __syncthreads();   // protect V dbuf + P before next chunk
    }

    // epilogue: O (final, P already normalized) -> g_ahi/g_alo
    #pragma unroll
    for (int nn = 0; nn < 4; nn++)
    #pragma unroll
    for (int ch = 0; ch < 2; ch++) {
        const int row = wm2 * 16 + ch * 8 + g;
        const int col = wn2 * 32 + nn * 8 + cc * 2;
        const size_t base = ((size_t)(b * L_ + q0 + row)) * D_ + h * HD_ + col;
        float v0 = o[nn][2 * ch], v1 = o[nn][2 * ch + 1];
        uint32_t hw = packhl(v0, v1);
        *(uint32_t*)(g_ahi + base) = hw;
        *(uint32_t*)(g_alo + base) = packres(v0, v1, hw);
    }
}

extern "C" void kernel_launch(void* const* d_in, const int* in_sizes, int n_in,
                              void* d_out, int out_size) {
    const float* x  = (const float*)d_in[0];
    // d_in[1] = key_indices: unused by the reference computation
    const float* bo = (const float*)d_in[6];
    float* out = (float*)d_out;
    float* A   = out + (size_t)M_ * D_;

    cudaFuncSetAttribute(gemm_mma<1>, cudaFuncAttributeMaxDynamicSharedMemorySize, GSM_BYTES);
    cudaFuncSetAttribute(gemm_mma<0>, cudaFuncAttributeMaxDynamicSharedMemorySize, GSM_BYTES);
    cudaFuncSetAttribute(attn_mma,    cudaFuncAttributeMaxDynamicSharedMemorySize, ASM_BYTES);

    // bf16 hi/lo splits of x and the 4 weights
    split_kernel<<<(M_*D_/4 + 255)/256, 256>>>(x, 0, 0, M_*D_/4);
    for (int z = 0; z < 4; z++)
        split_kernel<<<(D_*D_/4 + 255)/256, 256>>>((const float*)d_in[2 + z], 1, z, D_*D_/4);

    // q,k,v projections (bf16 3-term) -> q (pre-scaled)/k/v fp16
    gemm_mma<1><<<dim3(8, 64, 3), 256, GSM_BYTES>>>(nullptr, nullptr);

    // two-phase attention: A + attn output
    attn_mma<<<dim3(32, 16, 4), 256, ASM_BYTES>>>(A);

    // output projection + bias (bf16 3-term)
    gemm_mma<0><<<dim3(8, 64, 1), 256, GSM_BYTES>>>(bo, out);
}

// round 14
// speedup vs baseline: 1.4426x; 1.1146x over previous
#include <cuda_runtime.h>
#include <cuda_bf16.h>
#include <cuda_fp16.h>
#include <cstdint>

#define B_  4
#define L_  2048
#define D_  1024
#define H_  16
#define HD_ 64
#define M_  (B_*L_)   // 8192

// ---------------- scratch (__device__ globals; no allocs allowed) ----------------
__device__ __half g_xh16[(size_t)M_*D_], g_xl16[(size_t)M_*D_];
__device__ __half g_w16[(size_t)4*D_*D_];
__device__ __half g_q16[(size_t)B_*H_*L_*HD_];   // pre-scaled by 0.125
__device__ __half g_k16[(size_t)B_*H_*L_*HD_];
__device__ __half g_v16[(size_t)B_*H_*L_*HD_];
__device__ __half g_ah16[(size_t)M_*D_], g_al16[(size_t)M_*D_];
__device__ __half g_u[(size_t)B_*H_*L_*L_];   // exp(s - m_running) scratch (fp16)

// ---------------- helpers ----------------
__device__ __forceinline__ uint32_t smem_u32(const void* p) {
    uint32_t a;
    asm("{ .reg .u64 t; cvta.to.shared.u64 t, %1; cvt.u32.u64 %0, t; }" : "=r"(a) : "l"(p));
    return a;
}
__device__ __forceinline__ void cpasync16(uint32_t dst, const void* src) {
    asm volatile("cp.async.cg.shared.global [%0], [%1], 16;" :: "r"(dst), "l"(src));
}
__device__ __forceinline__ void mma16816f(float* d, const uint32_t* a, const uint32_t* b) {
    asm volatile(
        "mma.sync.aligned.m16n8k16.row.col.f32.f16.f16.f32 "
        "{%0,%1,%2,%3}, {%4,%5,%6,%7}, {%8,%9}, {%0,%1,%2,%3};"
        : "+f"(d[0]), "+f"(d[1]), "+f"(d[2]), "+f"(d[3])
        : "r"(a[0]), "r"(a[1]), "r"(a[2]), "r"(a[3]), "r"(b[0]), "r"(b[1]));
}
__device__ __forceinline__ void ldm4(uint32_t* r, uint32_t a) {
    asm volatile("ldmatrix.sync.aligned.m8n8.x4.shared.b16 {%0,%1,%2,%3}, [%4];"
        : "=r"(r[0]), "=r"(r[1]), "=r"(r[2]), "=r"(r[3]) : "r"(a));
}
__device__ __forceinline__ void ldm4t(uint32_t* r, uint32_t a) {
    asm volatile("ldmatrix.sync.aligned.m8n8.x4.trans.shared.b16 {%0,%1,%2,%3}, [%4];"
        : "=r"(r[0]), "=r"(r[1]), "=r"(r[2]), "=r"(r[3]) : "r"(a));
}
__device__ __forceinline__ uint32_t ldmA_addr(uint32_t base, int S, int row0, int lane) {
    int lr = lane & 7, sel = lane >> 3;
    return base + (uint32_t)((row0 + lr + (sel & 1) * 8) * S + (sel & 2) * 2) * 4;
}
__device__ __forceinline__ uint32_t ldmB_addr(uint32_t base, int S, int n0, int lane) {
    int lr = lane & 7, sel = lane >> 3;
    return base + (uint32_t)((n0 + lr + (sel >> 1) * 8) * S + (sel & 1) * 4) * 4;
}
__device__ __forceinline__ uint32_t ldmBT_addr(uint32_t base, int S, int n0, int lane) {
    int lr = lane & 7, sel = lane >> 3;
    return base + (uint32_t)((lr + (sel & 1) * 8) * S + (n0 + (sel >> 1) * 8) / 2) * 4;
}
__device__ __forceinline__ uint32_t pack16(float a, float b) {   // fp16 pair
    __half2 t; t.x = __float2half_rn(a); t.y = __float2half_rn(b);
    return *(uint32_t*)&t;
}
__device__ __forceinline__ uint32_t packres16(float a, float b, uint32_t hw) {
    __half2 hv = *(__half2*)&hw;
    return pack16(a - __half2float(hv.x), b - __half2float(hv.y));
}

// ---------------- fp32 -> fp16 split (x hi/lo; weights single) ----------------
__global__ __launch_bounds__(256) void split_kernel(const float* __restrict__ src, int sel, int z, int n4)
{
    int i = blockIdx.x * blockDim.x + threadIdx.x;
    if (i >= n4) return;
    float4 v = ((const float4*)src)[i];
    uint32_t h0 = pack16(v.x, v.y), h1 = pack16(v.z, v.w);
    if (sel == 0) {
        uint32_t l0 = packres16(v.x, v.y, h0), l1 = packres16(v.z, v.w, h1);
        ((uint32_t*)(g_xh16 + 4 * (size_t)i))[0] = h0;
        ((uint32_t*)(g_xh16 + 4 * (size_t)i))[1] = h1;
        ((uint32_t*)(g_xl16 + 4 * (size_t)i))[0] = l0;
        ((uint32_t*)(g_xl16 + 4 * (size_t)i))[1] = l1;
    } else {
        __half* w = g_w16 + (size_t)z * D_ * D_;
        ((uint32_t*)(w + 4 * (size_t)i))[0] = h0;
        ((uint32_t*)(w + 4 * (size_t)i))[1] = h1;
    }
}

// ---------------- HMMA GEMM (fp16 2-term): C[m,n] = sum_k X[m,k]*W[n,k] ----------------
#define SRW  36
#define MATW (128*SRW)
#define BUFW (3*MATW)
#define GSM_BYTES (2*BUFW*4)   // 110592

template<int MODE>
__global__ __launch_bounds__(256) void gemm_mma(const float* __restrict__ bias, float* __restrict__ Out)
{
    extern __shared__ char smch[];
    const uint32_t sb = smem_u32(smch);

    const int tid = threadIdx.x, lane = tid & 31, wid = tid >> 5;
    const int wm = wid & 3, wn = wid >> 2;
    const int g = lane >> 2, cc = lane & 3;
    const int n0 = blockIdx.x * 128, m0 = blockIdx.y * 128;

    const __half *Ahp, *Alp, *Wp;
    int z = 0;
    if (MODE == 1) {
        z = blockIdx.z;
        Ahp = g_xh16; Alp = g_xl16;
        Wp = g_w16 + (size_t)z * D_ * D_;
    } else {
        Ahp = g_ah16; Alp = g_al16;
        Wp = g_w16 + (size_t)3 * D_ * D_;
    }

    const int r = tid >> 1, half = tid & 1;
    const size_t garow = (size_t)(m0 + r) * D_ + half * 32;
    const size_t gbrow = (size_t)(n0 + r) * D_ + half * 32;
    const uint32_t sdst = sb + (uint32_t)(r * SRW + half * 16) * 4;

    auto issue_chunk = [&](int c) {
        const int k0 = c * 64;
        const uint32_t d0 = sdst + (uint32_t)((c & 1) * BUFW) * 4;
        const __half* pa = Ahp + garow + k0;
        const __half* pl = Alp + garow + k0;
        const __half* pb = Wp  + gbrow + k0;
        #pragma unroll
        for (int j = 0; j < 4; j++) {
            cpasync16(d0 + j * 16,                 pa + j * 8);
            cpasync16(d0 + MATW * 4 + j * 16,      pl + j * 8);
            cpasync16(d0 + 2 * MATW * 4 + j * 16,  pb + j * 8);
        }
    };

    float d[2][8][4] = {};

    issue_chunk(0);
    asm volatile("cp.async.commit_group;" ::: "memory");

    for (int c = 0; c < 16; c++) {
        if (c < 15) {
            issue_chunk(c + 1);
            asm volatile("cp.async.commit_group;" ::: "memory");
            asm volatile("cp.async.wait_group 1;" ::: "memory");
        } else {
            asm volatile("cp.async.wait_group 0;" ::: "memory");
        }
        __syncthreads();

        const uint32_t bufb = sb + (uint32_t)((c & 1) * BUFW) * 4;
        const uint32_t aA0 = ldmA_addr(bufb, SRW, wm * 32, lane);
        const uint32_t aA1 = ldmA_addr(bufb, SRW, wm * 32 + 16, lane);
        uint32_t bB[2][2];
        #pragma unroll
        for (int nq = 0; nq < 2; nq++)
            #pragma unroll
            for (int pr = 0; pr < 2; pr++)
                bB[nq][pr] = ldmB_addr(bufb + 2 * MATW * 4, SRW, wn * 64 + nq * 32 + pr * 16, lane);

        #pragma unroll
        for (int ks = 0; ks < 4; ks++) {
            uint32_t ah[2][4], al[2][4];
            ldm4(ah[0], aA0 + ks * 32);
            ldm4(ah[1], aA1 + ks * 32);
            ldm4(al[0], aA0 + MATW * 4 + ks * 32);
            ldm4(al[1], aA1 + MATW * 4 + ks * 32);
            #pragma unroll
            for (int nq = 0; nq < 2; nq++)
                #pragma unroll
                for (int pr = 0; pr < 2; pr++) {
                    uint32_t bp[4];
                    ldm4(bp, bB[nq][pr] + ks * 32);
                    #pragma unroll
                    for (int hf = 0; hf < 2; hf++)
                        #pragma unroll
                        for (int mi = 0; mi < 2; mi++) {
                            float* dd = d[mi][nq * 4 + pr * 2 + hf];
                            mma16816f(dd, ah[mi], bp + hf * 2);
                            mma16816f(dd, al[mi], bp + hf * 2);
                        }
                }
        }
        __syncthreads();
    }

    // epilogue
    #pragma unroll
    for (int mi = 0; mi < 2; mi++) {
        const int row = m0 + wm * 32 + mi * 16 + g;
        #pragma unroll
        for (int ni = 0; ni < 8; ni++) {
            const int col = n0 + wn * 64 + ni * 8 + cc * 2;
            float* dd = d[mi][ni];
            if (MODE == 1) {
                int b = row >> 11, l = row & (L_ - 1);
                int hh = col >> 6, dp = col & 63;
                size_t base = ((size_t)(b * H_ + hh) * L_ + l) * HD_ + dp;
                if (z == 0) {
                    *(uint32_t*)(g_q16 + base)           = pack16(dd[0] * 0.125f, dd[1] * 0.125f);
                    *(uint32_t*)(g_q16 + base + 8 * HD_) = pack16(dd[2] * 0.125f, dd[3] * 0.125f);
                } else {
                    __half* dst = (z == 1) ? g_k16 : g_v16;
                    *(uint32_t*)(dst + base)           = pack16(dd[0], dd[1]);
                    *(uint32_t*)(dst + base + 8 * HD_) = pack16(dd[2], dd[3]);
                }
            } else {
                float bx = bias[col], by = bias[col + 1];
                *(float2*)(Out + (size_t)row * D_ + col) =
                    make_float2(dd[0] + bx, dd[1] + by);
                *(float2*)(Out + (size_t)(row + 8) * D_ + col) =
                    make_float2(dd[2] + bx, dd[3] + by);
            }
        }
    }
}

// ---------------- two-phase tensor-core attention (fp16 1-term, u scratch) ----------------
// CTA = (b, h, 64 q-rows), 16 chunks of 128 keys.
// Phase 1: S = Q K^T (fp16, q pre-scaled), row max -> m_run, u = exp(s - m_run) once,
//          l maintained in registers (tid<64) with the Sum(u) term deferred one chunk.
// Phase 2: p = u * exp(mc - m)/l (thread-linear elementwise), A written, P fp16 -> PV.
#define SQW  36
#define WKV  2304             // K/V double buffer: 2 x 4608 words
#define WPP  11520            // P: 64 x 68 words
#define SPW  68
#define ASM_BYTES (15872*4)   // 63488

__global__ __launch_bounds__(256) void attn_mma(float* __restrict__ A)
{
    extern __shared__ uint32_t s32[];
    __shared__ float ms[64], ls[64], pm[64][4], pe_s[64][4];
    __shared__ float fc[16][64];

    const int tid = threadIdx.x, lane = tid & 31, wid = tid >> 5;
    const int g = lane >> 2, cc = lane & 3;
    const int wm = wid & 1,  wn = wid >> 1;    // phase 1: 2m x 4n
    const int wm2 = wid & 3, wn2 = wid >> 2;   // phase 2: 4m x 2n
    const int q0 = blockIdx.x * 64, h = blockIdx.y, b = blockIdx.z;
    const int bh = b * H_ + h;
    const __half* qp = g_q16 + (size_t)bh * L_ * HD_;
    const __half* kp = g_k16 + (size_t)bh * L_ * HD_;
    const __half* vp = g_v16 + (size_t)bh * L_ * HD_;
    __half* ug = g_u + ((size_t)bh * L_ + q0) * L_;
    float* Ar = A + ((size_t)bh * L_ + q0) * L_;
    const uint32_t sb = smem_u32(s32);

    // Q 64x64 fp16 -> smem
    {
        const int r = tid >> 2, qseg = tid & 3;
        #pragma unroll
        for (int j = 0; j < 2; j++) {
            const int s0 = qseg * 2 + j;
            *(uint4*)&s32[r * SQW + s0 * 4] = *(const uint4*)(qp + (size_t)(q0 + r) * HD_ + s0 * 8);
        }
    }
    if (tid < 64) { pe_s[tid][0] = 0.f; pe_s[tid][1] = 0.f; pe_s[tid][2] = 0.f; pe_s[tid][3] = 0.f; }
    float m_run = -1e30f, l_run = 0.f;   // live in threads tid<64

    auto loadK = [&](int kt) {
        const int r = tid >> 1, half = tid & 1;
        const uint32_t bo = WKV + (kt & 1) * 4608;
        const __half* src = kp + (size_t)(kt * 128 + r) * HD_ + half * 32;
        const uint32_t dst = sb + (bo + r * SQW + half * 16) * 4;
        #pragma unroll
        for (int j = 0; j < 4; j++) cpasync16(dst + j * 16, src + j * 8);
    };
    auto loadV = [&](int kt) {
        const int r = tid >> 1, half = tid & 1;
        const uint32_t bo = WKV + (kt & 1) * 4608;
        const __half* src = vp + (size_t)(kt * 128 + r) * HD_ + half * 32;
        const uint32_t dst = sb + (bo + r * SQW + half * 16) * 4;
        #pragma unroll
        for (int j = 0; j < 4; j++) cpasync16(dst + j * 16, src + j * 8);
    };

    loadK(0);
    asm volatile("cp.async.commit_group;" ::: "memory");

    const uint32_t aQ0 = ldmA_addr(sb, SQW, wm * 32, lane);
    const uint32_t aQ1 = ldmA_addr(sb, SQW, wm * 32 + 16, lane);

    // ---------------- phase 1 ----------------
    for (int kt = 0; kt < 16; kt++) {
        if (kt < 15) {
            loadK(kt + 1);
            asm volatile("cp.async.commit_group;" ::: "memory");
            asm volatile("cp.async.wait_group 1;" ::: "memory");
        } else {
            asm volatile("cp.async.wait_group 0;" ::: "memory");
        }
        __syncthreads();   // S1: K(kt) visible

        const uint32_t Kb = sb + (WKV + (kt & 1) * 4608) * 4;
        uint32_t bK[2];
        #pragma unroll
        for (int pr = 0; pr < 2; pr++)
            bK[pr] = ldmB_addr(Kb, SQW, wn * 32 + pr * 16, lane);

        float d[2][4][4] = {};
        #pragma unroll
        for (int ks = 0; ks < 4; ks++) {
            uint32_t qf[2][4];
            ldm4(qf[0], aQ0 + ks * 32);
            ldm4(qf[1], aQ1 + ks * 32);
            #pragma unroll
            for (int pr = 0; pr < 2; pr++) {
                uint32_t bk[4];
                ldm4(bk, bK[pr] + ks * 32);
                #pragma unroll
                for (int hf = 0; hf < 2; hf++)
                    #pragma unroll
                    for (int mi = 0; mi < 2; mi++)
                        mma16816f(d[mi][pr * 2 + hf], qf[mi], bk + hf * 2);
            }
        }

        // row max only (no exp here)
        #pragma unroll
        for (int mi = 0; mi < 2; mi++)
        #pragma unroll
        for (int ch = 0; ch < 2; ch++) {
            const int row = wm * 32 + mi * 16 + ch * 8 + g;
            float mx = -1e30f;
            #pragma unroll
            for (int nb = 0; nb < 4; nb++)
                mx = fmaxf(mx, fmaxf(d[mi][nb][2 * ch], d[mi][nb][2 * ch + 1]));
            mx = fmaxf(mx, __shfl_xor_sync(0xffffffffu, mx, 1));
            mx = fmaxf(mx, __shfl_xor_sync(0xffffffffu, mx, 2));
            if (cc == 0) pm[row][wm * 0 + wn] = mx;
        }
        __syncthreads();   // S2: pm ready; pe_s(kt-1) ready (written before S1)

        if (tid < 64) {
            float mn = m_run;
            #pragma unroll
            for (int w = 0; w < 4; w++) mn = fmaxf(mn, pm[tid][w]);
            float s = pe_s[tid][0] + pe_s[tid][1] + pe_s[tid][2] + pe_s[tid][3];
            l_run = (l_run + s) * __expf(m_run - mn);   // kt=0: l=0, s=0
            m_run = mn;
            ms[tid] = mn; fc[kt][tid] = mn;
        }
        __syncthreads();   // S3: ms published

        // u = exp(s - m_run) once; accumulate row sums -> pe_s
        #pragma unroll
        for (int mi = 0; mi < 2; mi++)
        #pragma unroll
        for (int ch = 0; ch < 2; ch++) {
            const int row = wm * 32 + mi * 16 + ch * 8 + g;
            const float mrow = ms[row];
            float us = 0.f;
            #pragma unroll
            for (int nb = 0; nb < 4; nb++) {
                float p0 = __expf(d[mi][nb][2 * ch]     - mrow);
                float p1 = __expf(d[mi][nb][2 * ch + 1] - mrow);
                us += p0 + p1;
                *(uint32_t*)(ug + (size_t)row * L_ + kt * 128 + wn * 32 + nb * 8 + cc * 2)
                    = pack16(p0, p1);
            }
            us += __shfl_xor_sync(0xffffffffu, us, 1);
            us += __shfl_xor_sync(0xffffffffu, us, 2);
            if (cc == 0) pe_s[row][wn] = us;
        }
    }

    __syncthreads();   // pe_s(15) written
    if (tid < 64) {
        l_run += pe_s[tid][0] + pe_s[tid][1] + pe_s[tid][2] + pe_s[tid][3];
        ls[tid] = 1.0f / l_run;
    }
    loadV(0);
    asm volatile("cp.async.commit_group;" ::: "memory");
    __syncthreads();
    // fc[kt][row] = exp(mc - m_final) * inv_l
    for (int i = tid; i < 16 * 64; i += 256) {
        const int c = i >> 6, r2 = i & 63;
        fc[c][r2] = __expf(fc[c][r2] - ms[r2]) * ls[r2];
    }
    __syncthreads();

    // ---------------- phase 2 ----------------
    const uint32_t aP = ldmA_addr(sb + WPP * 4, SPW, wm2 * 16, lane);
    const int prow = tid >> 2;            // 0..63
    const int pcb  = (tid & 3) * 32;      // col block of 32 within chunk
    float o[4][4] = {};

    for (int kt = 0; kt < 16; kt++) {
        if (kt < 15) {
            loadV(kt + 1);
            asm volatile("cp.async.commit_group;" ::: "memory");
        }
        // build P: thread-linear elementwise p = u * fc; write final A; stage P fp16
        {
            const float f = fc[kt][prow];
            const __half* ub = ug + (size_t)prow * L_ + kt * 128 + pcb;
            float* ab = Ar + (size_t)prow * L_ + kt * 128 + pcb;
            uint32_t* pb = &s32[WPP + prow * SPW + (pcb >> 1)];
            #pragma unroll
            for (int j = 0; j < 4; j++) {
                uint4 up = *(const uint4*)(ub + j * 8);
                float2 t0 = __half22float2(*(__half2*)&up.x);
                float2 t1 = __half22float2(*(__half2*)&up.y);
                float2 t2 = __half22float2(*(__half2*)&up.z);
                float2 t3 = __half22float2(*(__half2*)&up.w);
                float a0 = t0.x * f, a1 = t0.y * f, a2 = t1.x * f, a3 = t1.y * f;
                float a4 = t2.x * f, a5 = t2.y * f, a6 = t3.x * f, a7 = t3.y * f;
                *(float4*)(ab + j * 8)     = make_float4(a0, a1, a2, a3);
                *(float4*)(ab + j * 8 + 4) = make_float4(a4, a5, a6, a7);
                *(uint4*)(pb + j * 4) = make_uint4(pack16(a0, a1), pack16(a2, a3),
                                                   pack16(a4, a5), pack16(a6, a7));
            }
        }
        if (kt < 15) asm volatile("cp.async.wait_group 1;" ::: "memory");
        else         asm volatile("cp.async.wait_group 0;" ::: "memory");
        __syncthreads();   // V(kt) visible + P staged

        const uint32_t Vb = sb + (WKV + (kt & 1) * 4608) * 4;
        uint32_t bV[2];
        #pragma unroll
        for (int np = 0; np < 2; np++)
            bV[np] = ldmBT_addr(Vb, SQW, wn2 * 32 + np * 16, lane);

        #pragma unroll
        for (int ks = 0; ks < 8; ks++) {
            uint32_t ap[4];
            ldm4(ap, aP + ks * 32);
            #pragma unroll
            for (int np = 0; np < 2; np++) {
                uint32_t bv[4];
                ldm4t(bv, bV[np] + ks * 16 * SQW * 4);
                #pragma unroll
                for (int hf = 0; hf < 2; hf++)
                    mma16816f(o[np * 2 + hf], ap, bv + hf * 2);
            }
        }
        __syncthreads();   // protect V dbuf + P before next chunk
    }

    // epilogue: O (final, P already normalized) -> g_ah16/g_al16 (fp16 hi/lo for out-proj)
    #pragma unroll
    for (int nn = 0; nn < 4; nn++)
    #pragma unroll
    for (int ch = 0; ch < 2; ch++) {
        const int row = wm2 * 16 + ch * 8 + g;
        const int col = wn2 * 32 + nn * 8 + cc * 2;
        const size_t base = ((size_t)(b * L_ + q0 + row)) * D_ + h * HD_ + col;
        float v0 = o[nn][2 * ch], v1 = o[nn][2 * ch + 1];
        uint32_t hw = pack16(v0, v1);
        *(uint32_t*)(g_ah16 + base) = hw;
        *(uint32_t*)(g_al16 + base) = packres16(v0, v1, hw);
    }
}

extern "C" void kernel_launch(void* const* d_in, const int* in_sizes, int n_in,
                              void* d_out, int out_size) {
    const float* x  = (const float*)d_in[0];
    // d_in[1] = key_indices: unused by the reference computation
    const float* bo = (const float*)d_in[6];
    float* out = (float*)d_out;
    float* A   = out + (size_t)M_ * D_;

    cudaFuncSetAttribute(gemm_mma<1>, cudaFuncAttributeMaxDynamicSharedMemorySize, GSM_BYTES);
    cudaFuncSetAttribute(gemm_mma<0>, cudaFuncAttributeMaxDynamicSharedMemorySize, GSM_BYTES);
    cudaFuncSetAttribute(attn_mma,    cudaFuncAttributeMaxDynamicSharedMemorySize, ASM_BYTES);

    // fp16 splits: x -> hi/lo, weights -> single
    split_kernel<<<(M_*D_/4 + 255)/256, 256>>>(x, 0, 0, M_*D_/4);
    for (int z = 0; z < 4; z++)
        split_kernel<<<(D_*D_/4 + 255)/256, 256>>>((const float*)d_in[2 + z], 1, z, D_*D_/4);

    // q,k,v projections (fp16 2-term) -> q (pre-scaled)/k/v fp16
    gemm_mma<1><<<dim3(8, 64, 3), 256, GSM_BYTES>>>(nullptr, nullptr);

    // two-phase attention: A + attn output (fp16 hi/lo)
    attn_mma<<<dim3(32, 16, 4), 256, ASM_BYTES>>>(A);

    // output projection + bias (fp16 2-term)
    gemm_mma<0><<<dim3(8, 64, 1), 256, GSM_BYTES>>>(bo, out);
}